// round 9
// baseline (speedup 1.0000x reference)
#include <cuda_runtime.h>
#include <cuda_fp16.h>
#include <math.h>
#include <stdint.h>

#define BB    64
#define TT    256
#define IDIM  512
#define HDIM  1024
#define G4    4096
#define GRID  128         // persistent blocks, all resident
#define HROW  72          // padded staging row stride in halfs (64 data + 8 pad)

// ---- device scratch ----
__device__ __half   g_h[2][BB * HDIM];    // double-buffered hidden state (fp16)
__device__ unsigned g_arrive;
__device__ unsigned g_gen;

// ---------------------------------------------------------------------------
__device__ __forceinline__ void mma_f16(float d[4],
    uint32_t a0, uint32_t a1, uint32_t a2, uint32_t a3,
    uint32_t b0, uint32_t b1)
{
    asm volatile(
        "mma.sync.aligned.m16n8k16.row.col.f32.f16.f16.f32 "
        "{%0,%1,%2,%3},{%4,%5,%6,%7},{%8,%9},{%0,%1,%2,%3};\n"
        : "+f"(d[0]), "+f"(d[1]), "+f"(d[2]), "+f"(d[3])
        : "r"(a0), "r"(a1), "r"(a2), "r"(a3), "r"(b0), "r"(b1));
}

__device__ __forceinline__ float sigf(float x) {
    return 1.f / (1.f + __expf(-x));
}

// ---------------------------------------------------------------------------
// Fused persistent LSTM: per block bx, per step t:
//   acc  = x[:,t,:] @ WiSlice      (K=512,  fp16 mma, 8 chunks)  [pre-barrier]
//   acc += h[t]     @ WhSlice      (K=1024, fp16 mma, 16 chunks) [post-barrier]
//   LSTM pointwise with c in registers, bias in registers.
// No g_gates buffer, no separate gemm kernel.
// ---------------------------------------------------------------------------
__global__ void __launch_bounds__(256, 1) lstm_fused_kernel(
    const float* __restrict__ X,    // [64, 256, 512]
    const float* __restrict__ Wi,   // [512, 4096]
    const float* __restrict__ bi,   // [4096]
    const float* __restrict__ bh,   // [4096]
    const float* __restrict__ Wh,   // [1024, 4096]
    float* __restrict__ out)        // Q_all | hT | cT
{
    extern __shared__ char smem[];
    uint2*  Wf  = (uint2*)smem;                          // [64 s][4 ct][32 l]  64 KB
    uint2*  Wif = (uint2*)(smem + 65536);                // [32 s][4 ct][32 l]  32 KB
    __half* Hs  = (__half*)(smem + 65536 + 32768);       // 2 * 64 * HROW halfs

    const int tid  = threadIdx.x;
    const int lane = tid & 31;
    const int wid  = tid >> 5;
    const int wm   = wid & 3;    // m16 group
    const int wn   = wid >> 2;   // n16 group
    const int bx   = blockIdx.x;

    // ---- build Wh fragments (proven R8 layout), once ----
    for (int e = tid; e < 64 * 4 * 32; e += 256) {
        int l  = e & 31;
        int ct = (e >> 5) & 3;
        int s  = e >> 7;
        int k  = s * 16 + (l & 3) * 2;
        int n  = ct * 8 + (l >> 2);
        int j  = bx * 8 + (n >> 2);
        int g  = n & 3;
        const float* Wcol = Wh + (size_t)g * 1024 + j;
        __half2 h0 = __floats2half2_rn(Wcol[(size_t)k * G4],
                                       Wcol[(size_t)(k + 1) * G4]);
        __half2 h1 = __floats2half2_rn(Wcol[(size_t)(k + 8) * G4],
                                       Wcol[(size_t)(k + 9) * G4]);
        uint2 v;
        v.x = *(uint32_t*)&h0;
        v.y = *(uint32_t*)&h1;
        Wf[e] = v;
    }
    // ---- build Wi fragments (same layout, K=512 -> s in [0,32)), once ----
    for (int e = tid; e < 32 * 4 * 32; e += 256) {
        int l  = e & 31;
        int ct = (e >> 5) & 3;
        int s  = e >> 7;
        int k  = s * 16 + (l & 3) * 2;
        int n  = ct * 8 + (l >> 2);
        int j  = bx * 8 + (n >> 2);
        int g  = n & 3;
        const float* Wcol = Wi + (size_t)g * 1024 + j;
        __half2 h0 = __floats2half2_rn(Wcol[(size_t)k * G4],
                                       Wcol[(size_t)(k + 1) * G4]);
        __half2 h1 = __floats2half2_rn(Wcol[(size_t)(k + 8) * G4],
                                       Wcol[(size_t)(k + 9) * G4]);
        uint2 v;
        v.x = *(uint32_t*)&h0;
        v.y = *(uint32_t*)&h1;
        Wif[e] = v;
    }
    __syncthreads();

    const int kq   = lane & 3;
    const int rowg = lane >> 2;
    const int odd  = lane & 1;
    const int bmy  = wm * 16 + rowg + (odd ? 8 : 0);
    const int jbase = bx * 8 + wn * 4 + (kq >> 1);
    const int arow  = wm * 16 + rowg;

    // ---- bias registers (bi + bh per owned gate col), once ----
    float bF[2], bI[2], bA[2], bO[2];
#pragma unroll
    for (int nt = 0; nt < 2; nt++) {
        int j = jbase + nt * 2;
        bF[nt] = bi[j]        + bh[j];
        bI[nt] = bi[1024 + j] + bh[1024 + j];
        bA[nt] = bi[2048 + j] + bh[2048 + j];
        bO[nt] = bi[3072 + j] + bh[3072 + j];
    }

    float creg[2] = {0.f, 0.f};

    // staging indices (64-row x 64-col chunks)
    const int sb = tid >> 3;     // row 0..31 (and +32 on 2nd pass)
    const int sg = tid & 7;      // 8-elem group within row

    for (int t = 0; t < TT; t++) {
        float acc[2][4] = {{0.f,0.f,0.f,0.f},{0.f,0.f,0.f,0.f}};

        // ================= gates phase: x[:,t,:] @ WiSlice (K=512) ==========
        // prefetch x chunk 0 (f32, convert on store)
        float4 px[2][2];
#pragma unroll
        for (int i = 0; i < 2; i++) {
            int b = sb + i * 32;
            const float* xr = X + ((size_t)b * TT + t) * IDIM + sg * 8;
            px[i][0] = __ldcg((const float4*)xr);
            px[i][1] = __ldcg((const float4*)(xr + 4));
        }

        int buf = 0;
        for (int ch = 0; ch < 8; ch++) {
            {
                __half* H = Hs + buf * (64 * HROW);
#pragma unroll
                for (int i = 0; i < 2; i++) {
                    int b = sb + i * 32;
                    __half2 q0 = __floats2half2_rn(px[i][0].x, px[i][0].y);
                    __half2 q1 = __floats2half2_rn(px[i][0].z, px[i][0].w);
                    __half2 q2 = __floats2half2_rn(px[i][1].x, px[i][1].y);
                    __half2 q3 = __floats2half2_rn(px[i][1].z, px[i][1].w);
                    uint4 v;
                    v.x = *(uint32_t*)&q0; v.y = *(uint32_t*)&q1;
                    v.z = *(uint32_t*)&q2; v.w = *(uint32_t*)&q3;
                    *(uint4*)(H + b * HROW + sg * 8) = v;
                }
            }
            __syncthreads();

            if (ch < 7) {
                int k0 = (ch + 1) * 64;
#pragma unroll
                for (int i = 0; i < 2; i++) {
                    int b = sb + i * 32;
                    const float* xr = X + ((size_t)b * TT + t) * IDIM + k0 + sg * 8;
                    px[i][0] = __ldcg((const float4*)xr);
                    px[i][1] = __ldcg((const float4*)(xr + 4));
                }
            }

            const __half* H = Hs + buf * (64 * HROW) + arow * HROW;
#pragma unroll
            for (int ks = 0; ks < 4; ks++) {
                int col = ks * 16 + kq * 2;
                uint32_t a0 = *(const uint32_t*)(H + col);
                uint32_t a1 = *(const uint32_t*)(H + 8 * HROW + col);
                uint32_t a2 = *(const uint32_t*)(H + col + 8);
                uint32_t a3 = *(const uint32_t*)(H + 8 * HROW + col + 8);
                int s = ch * 4 + ks;
#pragma unroll
                for (int nt = 0; nt < 2; nt++) {
                    uint2 bv = Wif[(s * 4 + wn * 2 + nt) * 32 + lane];
                    mma_f16(acc[nt], a0, a1, a2, a3, bv.x, bv.y);
                }
            }
            buf ^= 1;
        }

        // ================= recurrent phase: h[t] @ WhSlice (K=1024) =========
        if (t > 0) {
            // grid barrier (proven R5/R8 form; gates work above overlapped wait)
            __threadfence();
            __syncthreads();
            if (tid == 0) {
                unsigned a = atomicAdd(&g_arrive, 1u);
                if (a == GRID - 1u) {
                    g_arrive = 0u;
                    __threadfence();
                    atomicExch(&g_gen, (unsigned)t);
                } else {
                    while (atomicAdd(&g_gen, 0u) < (unsigned)t) { }
                }
            }
            __syncthreads();

            const __half* __restrict__ hin = g_h[t & 1];

            uint4 pf[2];
#pragma unroll
            for (int i = 0; i < 2; i++) {
                int b = sb + i * 32;
                pf[i] = __ldcg((const uint4*)(hin + (size_t)b * HDIM + sg * 8));
            }

            buf = 0;
            for (int ch = 0; ch < 16; ch++) {
                {
                    __half* H = Hs + buf * (64 * HROW);
#pragma unroll
                    for (int i = 0; i < 2; i++) {
                        int b = sb + i * 32;
                        *(uint4*)(H + b * HROW + sg * 8) = pf[i];
                    }
                }
                __syncthreads();

                if (ch < 15) {
                    int k0 = (ch + 1) * 64;
#pragma unroll
                    for (int i = 0; i < 2; i++) {
                        int b = sb + i * 32;
                        pf[i] = __ldcg((const uint4*)(hin + (size_t)b * HDIM + k0 + sg * 8));
                    }
                }

                const __half* H = Hs + buf * (64 * HROW) + arow * HROW;
#pragma unroll
                for (int ks = 0; ks < 4; ks++) {
                    int col = ks * 16 + kq * 2;
                    uint32_t a0 = *(const uint32_t*)(H + col);
                    uint32_t a1 = *(const uint32_t*)(H + 8 * HROW + col);
                    uint32_t a2 = *(const uint32_t*)(H + col + 8);
                    uint32_t a3 = *(const uint32_t*)(H + 8 * HROW + col + 8);
                    int s = ch * 4 + ks;
#pragma unroll
                    for (int nt = 0; nt < 2; nt++) {
                        uint2 bv = Wf[(s * 4 + wn * 2 + nt) * 32 + lane];
                        mma_f16(acc[nt], a0, a1, a2, a3, bv.x, bv.y);
                    }
                }
                buf ^= 1;
            }
            __syncthreads();
        } else {
            __syncthreads();   // protect Hs reuse across step boundary
        }

        // ================= epilogue =========================================
        __half* __restrict__ hout = g_h[(t + 1) & 1];
#pragma unroll
        for (int nt = 0; nt < 2; nt++) {
            float x0 = __shfl_xor_sync(0xffffffffu, acc[nt][0], 1);
            float x1 = __shfl_xor_sync(0xffffffffu, acc[nt][1], 1);
            float x2 = __shfl_xor_sync(0xffffffffu, acc[nt][2], 1);
            float x3 = __shfl_xor_sync(0xffffffffu, acc[nt][3], 1);

            float F, I, A, O;
            if (!odd) { F = acc[nt][0]; I = acc[nt][1]; A = x0; O = x1; }
            else      { F = x2;         I = x3;         A = acc[nt][2]; O = acc[nt][3]; }

            F += bF[nt]; I += bI[nt]; A += bA[nt]; O += bO[nt];

            float f = sigf(F);
            float i = sigf(I);
            float a = tanhf(A);
            float o = sigf(O);

            float c = f * creg[nt] + i * a;
            creg[nt] = c;
            float h = o * tanhf(c);

            int j = jbase + nt * 2;
            hout[(size_t)bmy * HDIM + j] = __float2half(h);
            out[((size_t)bmy * TT + t) * HDIM + j] = h;
            if (t == TT - 1) {
                size_t qsz = (size_t)BB * TT * HDIM;
                out[qsz + (size_t)bmy * HDIM + j]             = h;
                out[qsz + BB * HDIM + (size_t)bmy * HDIM + j] = c;
            }
        }
    }

    // ---- exit ritual: last block resets barrier state for graph replay ----
    __syncthreads();
    if (tid == 0) {
        __threadfence();
        unsigned a = atomicAdd(&g_arrive, 1u);
        if (a == GRID - 1u) {
            g_arrive = 0u;
            g_gen    = 0u;
            __threadfence();
        }
    }
}

// ---------------------------------------------------------------------------
extern "C" void kernel_launch(void* const* d_in, const int* in_sizes, int n_in,
                              void* d_out, int out_size) {
    const float* x  = (const float*)d_in[0];
    const float* Wi = (const float*)d_in[1];
    const float* bi = (const float*)d_in[2];
    const float* Wh = (const float*)d_in[3];
    const float* bh = (const float*)d_in[4];
    float* out = (float*)d_out;

    const int smem_bytes = 65536 + 32768 + 2 * 64 * HROW * 2;   // 116,736 B
    cudaFuncSetAttribute(lstm_fused_kernel,
                         cudaFuncAttributeMaxDynamicSharedMemorySize, smem_bytes);

    lstm_fused_kernel<<<GRID, 256, smem_bytes>>>(x, Wi, bi, bh, Wh, out);
}

// round 10
// speedup vs baseline: 1.5904x; 1.5904x over previous
#include <cuda_runtime.h>
#include <cuda_fp16.h>
#include <math.h>
#include <stdint.h>

#define BB    64
#define TT    256
#define IDIM  512
#define HDIM  1024
#define G4    4096        // 4*HDIM
#define GRID  128         // persistent blocks (<=148, all resident)
#define HROW  72          // padded sub-buffer row stride in halfs (64 data + 8 pad)
#define SUBSZ (64 * HROW) // halfs per 64x64 sub-buffer
#define CKB   256         // staging chunk width in halfs (4 sub-buffers)

// ---- device scratch ----
__device__ float    g_gates[(size_t)TT * BB * G4];  // [T][B][4H], bi+bh folded in
__device__ __half   g_h[2][BB * HDIM];              // double-buffered hidden state (fp16)
__device__ unsigned g_arrive;
__device__ unsigned g_gen;

// ---------------------------------------------------------------------------
// helpers
// ---------------------------------------------------------------------------
__device__ __forceinline__ float tf32r(float v) {
    uint32_t u;
    asm("cvt.rna.tf32.f32 %0, %1;" : "=r"(u) : "f"(v));
    return __uint_as_float(u);
}

__device__ __forceinline__ void mma_tf32(float d[4],
    uint32_t a0, uint32_t a1, uint32_t a2, uint32_t a3,
    uint32_t b0, uint32_t b1)
{
    asm volatile(
        "mma.sync.aligned.m16n8k8.row.col.f32.tf32.tf32.f32 "
        "{%0,%1,%2,%3},{%4,%5,%6,%7},{%8,%9},{%0,%1,%2,%3};\n"
        : "+f"(d[0]), "+f"(d[1]), "+f"(d[2]), "+f"(d[3])
        : "r"(a0), "r"(a1), "r"(a2), "r"(a3), "r"(b0), "r"(b1));
}

__device__ __forceinline__ void mma_f16(float d[4],
    uint32_t a0, uint32_t a1, uint32_t a2, uint32_t a3,
    uint32_t b0, uint32_t b1)
{
    asm volatile(
        "mma.sync.aligned.m16n8k16.row.col.f32.f16.f16.f32 "
        "{%0,%1,%2,%3},{%4,%5,%6,%7},{%8,%9},{%0,%1,%2,%3};\n"
        : "+f"(d[0]), "+f"(d[1]), "+f"(d[2]), "+f"(d[3])
        : "r"(a0), "r"(a1), "r"(a2), "r"(a3), "r"(b0), "r"(b1));
}

__device__ __forceinline__ float sigf(float x) {
    return 1.f / (1.f + __expf(-x));
}

// ---------------------------------------------------------------------------
// Phase 1: gates = x @ Wi + bi + bh   (tf32 MMA, unchanged from R8/proven)
// ---------------------------------------------------------------------------
__global__ void __launch_bounds__(256, 2) gemm_tc_kernel(
    const float* __restrict__ X,
    const float* __restrict__ Wi,
    const float* __restrict__ bi,
    const float* __restrict__ bh)
{
    if (blockIdx.x == 0 && blockIdx.y == 0 && threadIdx.x == 0) {
        g_arrive = 0u;
        g_gen    = 0u;
    }

    __shared__ float As[16][132];
    __shared__ float Bs[16][132];

    const int tid  = threadIdx.x;
    const int lane = tid & 31;
    const int w    = tid >> 5;
    const int wm   = w & 1;
    const int wn   = w >> 1;
    const int m0   = blockIdx.y * 128;
    const int n0   = blockIdx.x * 128;

    const int rowg = lane >> 2;
    const int kq   = lane & 3;

    const int aRow = tid >> 1;
    const int aCol = (tid & 1) * 8;
    const int bRow = tid >> 5;
    const int bCol = (tid & 31) * 4;

    float acc[4][4][4];
#pragma unroll
    for (int mi = 0; mi < 4; mi++)
#pragma unroll
        for (int ni = 0; ni < 4; ni++)
#pragma unroll
            for (int q = 0; q < 4; q++) acc[mi][ni][q] = 0.f;

    float4 pa0 = *(const float4*)(X + (size_t)(m0 + aRow) * IDIM + aCol);
    float4 pa1 = *(const float4*)(X + (size_t)(m0 + aRow) * IDIM + aCol + 4);
    float4 pb0 = *(const float4*)(Wi + (size_t)bRow * G4 + n0 + bCol);
    float4 pb1 = *(const float4*)(Wi + (size_t)(bRow + 8) * G4 + n0 + bCol);

    for (int k0 = 0; k0 < IDIM; k0 += 16) {
        As[aCol + 0][aRow] = tf32r(pa0.x);
        As[aCol + 1][aRow] = tf32r(pa0.y);
        As[aCol + 2][aRow] = tf32r(pa0.z);
        As[aCol + 3][aRow] = tf32r(pa0.w);
        As[aCol + 4][aRow] = tf32r(pa1.x);
        As[aCol + 5][aRow] = tf32r(pa1.y);
        As[aCol + 6][aRow] = tf32r(pa1.z);
        As[aCol + 7][aRow] = tf32r(pa1.w);
        {
            float4 b0 = pb0, b1 = pb1;
            b0.x = tf32r(b0.x); b0.y = tf32r(b0.y); b0.z = tf32r(b0.z); b0.w = tf32r(b0.w);
            b1.x = tf32r(b1.x); b1.y = tf32r(b1.y); b1.z = tf32r(b1.z); b1.w = tf32r(b1.w);
            *(float4*)(&Bs[bRow][bCol])     = b0;
            *(float4*)(&Bs[bRow + 8][bCol]) = b1;
        }
        __syncthreads();

        if (k0 + 16 < IDIM) {
            int kn = k0 + 16;
            pa0 = *(const float4*)(X + (size_t)(m0 + aRow) * IDIM + kn + aCol);
            pa1 = *(const float4*)(X + (size_t)(m0 + aRow) * IDIM + kn + aCol + 4);
            pb0 = *(const float4*)(Wi + (size_t)(kn + bRow) * G4 + n0 + bCol);
            pb1 = *(const float4*)(Wi + (size_t)(kn + bRow + 8) * G4 + n0 + bCol);
        }

#pragma unroll
        for (int ks = 0; ks < 2; ks++) {
            const int kb = ks * 8;
            uint32_t af[4][4], bf[4][2];
#pragma unroll
            for (int mi = 0; mi < 4; mi++) {
                int r = wm * 64 + mi * 16 + rowg;
                af[mi][0] = __float_as_uint(As[kb + kq][r]);
                af[mi][1] = __float_as_uint(As[kb + kq][r + 8]);
                af[mi][2] = __float_as_uint(As[kb + kq + 4][r]);
                af[mi][3] = __float_as_uint(As[kb + kq + 4][r + 8]);
            }
#pragma unroll
            for (int ni = 0; ni < 4; ni++) {
                int c = wn * 32 + ni * 8 + rowg;
                bf[ni][0] = __float_as_uint(Bs[kb + kq][c]);
                bf[ni][1] = __float_as_uint(Bs[kb + kq + 4][c]);
            }
#pragma unroll
            for (int mi = 0; mi < 4; mi++)
#pragma unroll
                for (int ni = 0; ni < 4; ni++)
                    mma_tf32(acc[mi][ni], af[mi][0], af[mi][1], af[mi][2], af[mi][3],
                             bf[ni][0], bf[ni][1]);
        }
        __syncthreads();
    }

#pragma unroll
    for (int ni = 0; ni < 4; ni++) {
        int n = n0 + wn * 32 + ni * 8 + 2 * kq;
        float bias0 = bi[n] + bh[n];
        float bias1 = bi[n + 1] + bh[n + 1];
#pragma unroll
        for (int mi = 0; mi < 4; mi++) {
            int m  = m0 + wm * 64 + mi * 16 + rowg;
            {
                int b = m >> 8, t = m & 255;
                float2 v = make_float2(acc[mi][ni][0] + bias0, acc[mi][ni][1] + bias1);
                *(float2*)(g_gates + (size_t)(t * BB + b) * G4 + n) = v;
            }
            {
                int m2 = m + 8;
                int b = m2 >> 8, t = m2 & 255;
                float2 v = make_float2(acc[mi][ni][2] + bias0, acc[mi][ni][3] + bias1);
                *(float2*)(g_gates + (size_t)(t * BB + b) * G4 + n) = v;
            }
        }
    }
}

// ---------------------------------------------------------------------------
// Phase 2: persistent LSTM recurrence (fp16 mma, R8 skeleton).
// ONLY change vs R8: staging chunk widened 64 -> 256 cols as FOUR proven
// 64x72 sub-buffers => 4 block syncs per step instead of 16, and 32
// uninterrupted mma k-steps between syncs.
// ---------------------------------------------------------------------------
__global__ void __launch_bounds__(256, 1) lstm_persist_kernel(
    const float* __restrict__ Wh,   // [1024, 4096]
    float* __restrict__ out)        // Q_all | hT | cT
{
    extern __shared__ char smem[];
    uint2*  Wf = (uint2*)smem;                       // [64 s][4 ct][32 lanes] = 64 KB
    __half* Hs = (__half*)(smem + 65536);            // 2 * 4 * SUBSZ halfs (73,728 B)

    const int tid  = threadIdx.x;
    const int lane = tid & 31;
    const int wid  = tid >> 5;
    const int wm   = wid & 3;
    const int wn   = wid >> 2;
    const int bx   = blockIdx.x;

    // build Wf (fp16 B-fragments for m16n8k16), once -- identical to R8
    for (int e = tid; e < 64 * 4 * 32; e += 256) {
        int l  = e & 31;
        int ct = (e >> 5) & 3;
        int s  = e >> 7;
        int k  = s * 16 + (l & 3) * 2;
        int n  = ct * 8 + (l >> 2);
        int j  = bx * 8 + (n >> 2);
        int g  = n & 3;
        const float* Wcol = Wh + (size_t)g * 1024 + j;
        __half2 h0 = __floats2half2_rn(Wcol[(size_t)k * G4],
                                       Wcol[(size_t)(k + 1) * G4]);
        __half2 h1 = __floats2half2_rn(Wcol[(size_t)(k + 8) * G4],
                                       Wcol[(size_t)(k + 9) * G4]);
        uint2 v;
        v.x = *(uint32_t*)&h0;
        v.y = *(uint32_t*)&h1;
        Wf[e] = v;
    }
    __syncthreads();

    const int kq   = lane & 3;
    const int rowg = lane >> 2;
    const int odd  = lane & 1;
    const int bmy  = wm * 16 + rowg + (odd ? 8 : 0);
    const int jbase = bx * 8 + wn * 4 + (kq >> 1);

    float creg[2] = {0.f, 0.f};
    const int arow = wm * 16 + rowg;

    // staging indices: rows {sb, sb+32}, 16B group sg within each 64-col sub
    const int sb = tid >> 3;     // 0..31
    const int sg = tid & 7;      // 0..7

    for (int t = 0; t < TT; t++) {
        float acc[2][4] = {{0.f,0.f,0.f,0.f},{0.f,0.f,0.f,0.f}};

        const float* __restrict__ gt = g_gates + (size_t)t * BB * G4;
        float gF[2], gI[2], gA[2], gO[2];
#pragma unroll
        for (int nt = 0; nt < 2; nt++) {
            int j = jbase + nt * 2;
            gF[nt] = __ldcg(gt + (size_t)bmy * G4 + j);
            gI[nt] = __ldcg(gt + (size_t)bmy * G4 + 1024 + j);
            gA[nt] = __ldcg(gt + (size_t)bmy * G4 + 2048 + j);
            gO[nt] = __ldcg(gt + (size_t)bmy * G4 + 3072 + j);
        }

        if (t > 0) {
            // ---- grid barrier (proven R5/R8 form) ----
            __threadfence();
            __syncthreads();
            if (tid == 0) {
                unsigned a = atomicAdd(&g_arrive, 1u);
                if (a == GRID - 1u) {
                    g_arrive = 0u;
                    __threadfence();
                    atomicExch(&g_gen, (unsigned)t);
                } else {
                    while (atomicAdd(&g_gen, 0u) < (unsigned)t) { }
                }
            }
            __syncthreads();

            const __half* __restrict__ hin = g_h[t & 1];

            // prefetch chunk 0: 8 x uint4 per thread (2 rows x 4 sub-blocks)
            uint4 pf[2][4];
#pragma unroll
            for (int i = 0; i < 2; i++) {
                int b = sb + i * 32;
#pragma unroll
                for (int q = 0; q < 4; q++)
                    pf[i][q] = __ldcg((const uint4*)(hin + (size_t)b * HDIM
                                                     + q * 64 + sg * 8));
            }

            int buf = 0;
            for (int ch = 0; ch < 4; ch++) {
                // store chunk: each uint4 into its 64x72 sub-buffer (R8 layout)
                {
                    __half* H = Hs + buf * (4 * SUBSZ);
#pragma unroll
                    for (int i = 0; i < 2; i++) {
                        int b = sb + i * 32;
#pragma unroll
                        for (int q = 0; q < 4; q++)
                            *(uint4*)(H + q * SUBSZ + b * HROW + sg * 8) = pf[i][q];
                    }
                }
                __syncthreads();

                // prefetch next chunk
                if (ch < 3) {
                    int k0 = (ch + 1) * CKB;
#pragma unroll
                    for (int i = 0; i < 2; i++) {
                        int b = sb + i * 32;
#pragma unroll
                        for (int q = 0; q < 4; q++)
                            pf[i][q] = __ldcg((const uint4*)(hin + (size_t)b * HDIM
                                                             + k0 + q * 64 + sg * 8));
                    }
                }

                // 16 fp16 mma k-steps on this chunk (4 per sub-buffer)
                const __half* Hbase = Hs + buf * (4 * SUBSZ) + arow * HROW;
#pragma unroll
                for (int ks = 0; ks < 16; ks++) {
                    int q   = ks >> 2;
                    int kss = ks & 3;
                    const __half* H = Hbase + q * SUBSZ;
                    int col = kss * 16 + kq * 2;
                    uint32_t a0 = *(const uint32_t*)(H + col);
                    uint32_t a1 = *(const uint32_t*)(H + 8 * HROW + col);
                    uint32_t a2 = *(const uint32_t*)(H + col + 8);
                    uint32_t a3 = *(const uint32_t*)(H + 8 * HROW + col + 8);
                    int s = ch * 16 + ks;
#pragma unroll
                    for (int nt = 0; nt < 2; nt++) {
                        uint2 bv = Wf[(s * 4 + wn * 2 + nt) * 32 + lane];
                        mma_f16(acc[nt], a0, a1, a2, a3, bv.x, bv.y);
                    }
                }
                buf ^= 1;
            }
            __syncthreads();
        }

        // ---- epilogue (unchanged) ----
        __half* __restrict__ hout = g_h[(t + 1) & 1];
#pragma unroll
        for (int nt = 0; nt < 2; nt++) {
            float x0 = __shfl_xor_sync(0xffffffffu, acc[nt][0], 1);
            float x1 = __shfl_xor_sync(0xffffffffu, acc[nt][1], 1);
            float x2 = __shfl_xor_sync(0xffffffffu, acc[nt][2], 1);
            float x3 = __shfl_xor_sync(0xffffffffu, acc[nt][3], 1);

            float F, I, A, O;
            if (!odd) { F = acc[nt][0]; I = acc[nt][1]; A = x0; O = x1; }
            else      { F = x2;         I = x3;         A = acc[nt][2]; O = acc[nt][3]; }

            F += gF[nt]; I += gI[nt]; A += gA[nt]; O += gO[nt];

            float f = sigf(F);
            float i = sigf(I);
            float a = tanhf(A);
            float o = sigf(O);

            float c = f * creg[nt] + i * a;
            creg[nt] = c;
            float h = o * tanhf(c);

            int j = jbase + nt * 2;
            hout[(size_t)bmy * HDIM + j] = __float2half(h);
            out[((size_t)bmy * TT + t) * HDIM + j] = h;
            if (t == TT - 1) {
                size_t qsz = (size_t)BB * TT * HDIM;
                out[qsz + (size_t)bmy * HDIM + j]             = h;
                out[qsz + BB * HDIM + (size_t)bmy * HDIM + j] = c;
            }
        }
    }
}

// ---------------------------------------------------------------------------
extern "C" void kernel_launch(void* const* d_in, const int* in_sizes, int n_in,
                              void* d_out, int out_size) {
    const float* x  = (const float*)d_in[0];
    const float* Wi = (const float*)d_in[1];
    const float* bi = (const float*)d_in[2];
    const float* Wh = (const float*)d_in[3];
    const float* bh = (const float*)d_in[4];
    float* out = (float*)d_out;

    const int smem_bytes = 65536 + 2 * 4 * SUBSZ * 2;   // 139,264 B
    cudaFuncSetAttribute(lstm_persist_kernel,
                         cudaFuncAttributeMaxDynamicSharedMemorySize, smem_bytes);

    gemm_tc_kernel<<<dim3(G4 / 128, (BB * TT) / 128), 256>>>(x, Wi, bi, bh);
    lstm_persist_kernel<<<GRID, 256, smem_bytes>>>(Wh, out);
}